// round 12
// baseline (speedup 1.0000x reference)
#include <cuda_runtime.h>
#include <math.h>

#define TT 512
#define BB 64
#define HH 256
#define KK 11
#define STARTT 9
#define STOPP 10

typedef unsigned long long u64;

// ---------------- scratch (device globals: allocation-free rule) -----------
__device__ float d_XWF[(size_t)TT * BB * 1024];   // [T][B][4H] fwd input proj
__device__ float d_XWB[(size_t)TT * BB * 1024];   // [T][B][4H] bwd input proj
__device__ float d_H0[(size_t)BB * TT * 512];     // [B*T][2H] layer0 out (fwd|bwd)
__device__ float d_H1[(size_t)BB * TT * 512];     // [B*T][2H] layer1 out
__device__ float d_FEATS[(size_t)BB * TT * KK];   // [B*T][K] emissions

// ---------------- helpers --------------------------------------------------
__device__ __forceinline__ unsigned smem_u32(const void* p) {
    return (unsigned)__cvta_generic_to_shared(p);
}
__device__ __forceinline__ void st_cluster_f32(unsigned laddr, int rank, float v) {
    unsigned raddr;
    asm volatile("mapa.shared::cluster.u32 %0, %1, %2;" : "=r"(raddr) : "r"(laddr), "r"(rank));
    asm volatile("st.shared::cluster.f32 [%0], %1;" :: "r"(raddr), "f"(v) : "memory");
}
__device__ __forceinline__ void cluster_arrive() {
    asm volatile("barrier.cluster.arrive.aligned;" ::: "memory");
}
__device__ __forceinline__ void cluster_wait() {
    asm volatile("barrier.cluster.wait.aligned;" ::: "memory");
}
__device__ __forceinline__ float fast_sigmoid(float x) {
    return __fdividef(1.f, 1.f + __expf(-x));
}
__device__ __forceinline__ float fast_tanh(float x) {
    float xc = fminf(15.f, fmaxf(-15.f, x));
    float e = __expf(2.f * xc);
    return __fdividef(e - 1.f, e + 1.f);
}

// ---- packed fp32x2 (Blackwell FFMA2) --------------------------------------
__device__ __forceinline__ u64 pack2(float lo, float hi) {
    u64 r; asm("mov.b64 %0, {%1, %2};" : "=l"(r) : "f"(lo), "f"(hi)); return r;
}
__device__ __forceinline__ float2 unpack2(u64 v) {
    float2 f; asm("mov.b64 {%0, %1}, %2;" : "=f"(f.x), "=f"(f.y) : "l"(v)); return f;
}
__device__ __forceinline__ void fma2(u64& d, u64 a, u64 b) {
    asm("fma.rn.f32x2 %0, %1, %2, %0;" : "+l"(d) : "l"(a), "l"(b));
}
__device__ __forceinline__ u64 add2(u64 a, u64 b) {
    u64 r; asm("add.rn.f32x2 %0, %1, %2;" : "=l"(r) : "l"(a), "l"(b)); return r;
}

// ---------------------------------------------------------------------------
// Input projection: XW[dir][t][b][n] = x[m] . W[n][:] + bias[n]
// Accumulators packed along M: accp[p][j] = (row 2p, row 2p+1) x col j.
// A-pairs load FREE as ulonglong2 from smem (adjacent m); only B is dup'd.
// 32 u64 accs = 64 regs -> 2 CTAs/SM via __launch_bounds__(256,2).
// ---------------------------------------------------------------------------
__global__ __launch_bounds__(256, 2) void proj_kernel(
    const int* __restrict__ sent, const float* __restrict__ emb,
    const float* __restrict__ Wf, const float* __restrict__ bf,
    const float* __restrict__ Wb, const float* __restrict__ bb_,
    int K, int layer)
{
    __shared__ float As[2][16][128];
    __shared__ float Bs[2][16][128];
    __shared__ int srow[128];

    int tid = threadIdx.x;
    int bx  = blockIdx.x;          // 0..15
    int by  = blockIdx.y;          // 0..255
    int m0  = by * 128;
    int dirb = bx >> 3;
    int ncol = (bx & 7) * 128;

    const float* W    = dirb ? Wb  : Wf;
    const float* bias = dirb ? bb_ : bf;
    float*       XW   = dirb ? d_XWB : d_XWF;

    if (layer == 0 && tid < 128) srow[tid] = sent[m0 + tid];
    __syncthreads();

    int mi = tid >> 1;            // 0..127
    int ks = (tid & 1) * 8;       // 0 or 8

    const float* arow;
    if (layer == 0) arow = emb + (size_t)srow[mi] * 300;
    else            arow = d_H0 + (size_t)(m0 + mi) * 512;
    const float* wrow = W + (size_t)(ncol + mi) * K;

    int tm = tid >> 4, tn = tid & 15;

    // accp[p][j]: p=0..3 m-pairs {(tm*4,+1),(tm*4+2,+3),(64+tm*4,+1),(64+tm*4+2,+3)}
    //             j=0..7 cols  {tn*4+j}for j<4, {64+tn*4+j-4} for j>=4
    u64 accp[4][8];
#pragma unroll
    for (int p = 0; p < 4; p++)
#pragma unroll
        for (int j = 0; j < 8; j++) accp[p][j] = 0ull;

    const float4 z4 = make_float4(0.f, 0.f, 0.f, 0.f);
    int nk = (K + 15) >> 4;

    float4 pa0, pa1, pb0, pb1;
    {
        int k0 = ks;
        pa0 = (k0     < K) ? *(const float4*)(arow + k0)     : z4;
        pa1 = (k0 + 4 < K) ? *(const float4*)(arow + k0 + 4) : z4;
        pb0 = (k0     < K) ? *(const float4*)(wrow + k0)     : z4;
        pb1 = (k0 + 4 < K) ? *(const float4*)(wrow + k0 + 4) : z4;
    }
    As[0][ks + 0][mi] = pa0.x; As[0][ks + 1][mi] = pa0.y;
    As[0][ks + 2][mi] = pa0.z; As[0][ks + 3][mi] = pa0.w;
    As[0][ks + 4][mi] = pa1.x; As[0][ks + 5][mi] = pa1.y;
    As[0][ks + 6][mi] = pa1.z; As[0][ks + 7][mi] = pa1.w;
    Bs[0][ks + 0][mi] = pb0.x; Bs[0][ks + 1][mi] = pb0.y;
    Bs[0][ks + 2][mi] = pb0.z; Bs[0][ks + 3][mi] = pb0.w;
    Bs[0][ks + 4][mi] = pb1.x; Bs[0][ks + 5][mi] = pb1.y;
    Bs[0][ks + 6][mi] = pb1.z; Bs[0][ks + 7][mi] = pb1.w;
    __syncthreads();

    for (int it = 0; it < nk; ++it) {
        int cur = it & 1;

        if (it + 1 < nk) {
            int k0 = (it + 1) * 16 + ks;
            pa0 = (k0     < K) ? *(const float4*)(arow + k0)     : z4;
            pa1 = (k0 + 4 < K) ? *(const float4*)(arow + k0 + 4) : z4;
            pb0 = (k0     < K) ? *(const float4*)(wrow + k0)     : z4;
            pb1 = (k0 + 4 < K) ? *(const float4*)(wrow + k0 + 4) : z4;
        }

        const float (*Ac)[128] = As[cur];
        const float (*Bc)[128] = Bs[cur];
#pragma unroll
        for (int k = 0; k < 16; k++) {
            // a-pairs: adjacent m -> free 64-bit packed loads
            ulonglong2 ap0 = *(const ulonglong2*)&Ac[k][tm * 4];       // pairs p0,p1
            ulonglong2 ap1 = *(const ulonglong2*)&Ac[k][64 + tm * 4];  // pairs p2,p3
            float4 b0 = *(const float4*)&Bc[k][tn * 4];
            float4 b1 = *(const float4*)&Bc[k][64 + tn * 4];
            u64 bd[8];
            bd[0] = pack2(b0.x, b0.x); bd[1] = pack2(b0.y, b0.y);
            bd[2] = pack2(b0.z, b0.z); bd[3] = pack2(b0.w, b0.w);
            bd[4] = pack2(b1.x, b1.x); bd[5] = pack2(b1.y, b1.y);
            bd[6] = pack2(b1.z, b1.z); bd[7] = pack2(b1.w, b1.w);
            u64 ap[4] = {ap0.x, ap0.y, ap1.x, ap1.y};
#pragma unroll
            for (int p = 0; p < 4; p++)
#pragma unroll
                for (int j = 0; j < 8; j++)
                    fma2(accp[p][j], ap[p], bd[j]);
        }

        if (it + 1 < nk) {
            int nb = cur ^ 1;
            As[nb][ks + 0][mi] = pa0.x; As[nb][ks + 1][mi] = pa0.y;
            As[nb][ks + 2][mi] = pa0.z; As[nb][ks + 3][mi] = pa0.w;
            As[nb][ks + 4][mi] = pa1.x; As[nb][ks + 5][mi] = pa1.y;
            As[nb][ks + 6][mi] = pa1.z; As[nb][ks + 7][mi] = pa1.w;
            Bs[nb][ks + 0][mi] = pb0.x; Bs[nb][ks + 1][mi] = pb0.y;
            Bs[nb][ks + 2][mi] = pb0.z; Bs[nb][ks + 3][mi] = pb0.w;
            Bs[nb][ks + 4][mi] = pb1.x; Bs[nb][ks + 5][mi] = pb1.y;
            Bs[nb][ks + 6][mi] = pb1.z; Bs[nb][ks + 7][mi] = pb1.w;
            __syncthreads();
        }
    }

    // epilogue: row i of 8 -> pair p=i>>1 (or 2+((i-4)>>1)), .x even / .y odd
    float4 ba  = *(const float4*)&bias[ncol + tn * 4];
    float4 bb2 = *(const float4*)&bias[ncol + 64 + tn * 4];
#pragma unroll
    for (int i = 0; i < 8; i++) {
        int p   = (i < 4) ? (i >> 1) : (2 + ((i - 4) >> 1));
        bool odd = (i & 1) != 0;
        int mm = m0 + ((i < 4) ? (tm * 4 + i) : (64 + tm * 4 + (i - 4)));
        int b_ = mm >> 9, t_ = mm & 511;          // m = b*512 + t
        float* orow = XW + ((size_t)t_ * 64 + b_) * 1024 + ncol;
        float v[8];
#pragma unroll
        for (int j = 0; j < 8; j++) {
            float2 u = unpack2(accp[p][j]);
            v[j] = odd ? u.y : u.x;
        }
        float4 o1 = make_float4(v[0] + ba.x,  v[1] + ba.y,  v[2] + ba.z,  v[3] + ba.w);
        float4 o2 = make_float4(v[4] + bb2.x, v[5] + bb2.y, v[6] + bb2.z, v[7] + bb2.w);
        *(float4*)(orow + tn * 4)      = o1;
        *(float4*)(orow + 64 + tn * 4) = o2;
    }
}

// ---------------------------------------------------------------------------
// Recurrent LSTM (unchanged from R10). grid=128 CTAs, cluster 8, 256 thr.
// ---------------------------------------------------------------------------
__global__ __launch_bounds__(256) __cluster_dims__(8, 1, 1)
void rec_kernel(const float* __restrict__ whhF, const float* __restrict__ whhB, int outSel)
{
    __shared__ float hsm[2][8][288];   // [buf][batch][k padded: k + (k>>5)*4]

    int cta = blockIdx.x;
    int s   = cta & 7;
    int cl  = cta >> 3;
    int dir = cl >> 3;      // 0 fwd, 1 bwd
    int bg  = cl & 7;

    const float* XW   = dir ? d_XWB : d_XWF;
    const float* Whh  = dir ? whhB  : whhF;
    float*       Hout = outSel ? d_H1 : d_H0;

    int tid  = threadIdx.x;
    int w    = tid >> 5, lane = tid & 31;
    int jsub = lane >> 3, kr = lane & 7;
    int jl   = w * 4 + jsub;
    int jg   = s * 32 + jl;
    int b    = kr;
    int bglob = bg * 8 + b;

    // load 4 gate rows' k-slices, pack along gate pairs
    u64 Wp[2][8][4];
    {
        const float* w0 = Whh + (size_t)(0 * 256 + jg) * 256 + kr * 32;
        const float* w1 = Whh + (size_t)(1 * 256 + jg) * 256 + kr * 32;
        const float* w2 = Whh + (size_t)(2 * 256 + jg) * 256 + kr * 32;
        const float* w3 = Whh + (size_t)(3 * 256 + jg) * 256 + kr * 32;
#pragma unroll
        for (int q = 0; q < 8; q++) {
            float4 a = *(const float4*)(w0 + q * 4);
            float4 bq = *(const float4*)(w1 + q * 4);
            float4 cq = *(const float4*)(w2 + q * 4);
            float4 dq = *(const float4*)(w3 + q * 4);
            Wp[0][q][0] = pack2(a.x, bq.x); Wp[0][q][1] = pack2(a.y, bq.y);
            Wp[0][q][2] = pack2(a.z, bq.z); Wp[0][q][3] = pack2(a.w, bq.w);
            Wp[1][q][0] = pack2(cq.x, dq.x); Wp[1][q][1] = pack2(cq.y, dq.y);
            Wp[1][q][2] = pack2(cq.z, dq.z); Wp[1][q][3] = pack2(cq.w, dq.w);
        }
    }

    for (int i = tid; i < 2 * 8 * 288; i += 256) (&hsm[0][0][0])[i] = 0.f;
    float c = 0.f;
    __syncthreads();
    cluster_arrive();

    // prefetch xw for step 0 (overlaps barrier wait)
    int t0 = dir ? 511 : 0;
    const float* xwp = XW + ((size_t)t0 * 64 + bglob) * 1024 + jg;
    float xw0 = xwp[0], xw1 = xwp[256], xw2 = xwp[512], xw3 = xwp[768];

    cluster_wait();                    // zeros + peers ready

    int buf = 0;
    for (int step = 0; step < 512; ++step) {
        int t = dir ? (511 - step) : step;

        u64 accP[2][8];
#pragma unroll
        for (int p = 0; p < 2; p++)
#pragma unroll
            for (int q = 0; q < 8; q++) accP[p][q] = 0ull;

        const float* hb = &hsm[buf][0][0];
#pragma unroll
        for (int q = 0; q < 8; q++) {
#pragma unroll
            for (int bb2 = 0; bb2 < 8; bb2++) {
                float4 hv = *(const float4*)(hb + bb2 * 288 + kr * 36 + q * 4);
                u64 hx = pack2(hv.x, hv.x);
                u64 hy = pack2(hv.y, hv.y);
                u64 hz = pack2(hv.z, hv.z);
                u64 hw = pack2(hv.w, hv.w);
                fma2(accP[0][bb2], Wp[0][q][0], hx);
                fma2(accP[1][bb2], Wp[1][q][0], hx);
                fma2(accP[0][bb2], Wp[0][q][1], hy);
                fma2(accP[1][bb2], Wp[1][q][1], hy);
                fma2(accP[0][bb2], Wp[0][q][2], hz);
                fma2(accP[1][bb2], Wp[1][q][2], hz);
                fma2(accP[0][bb2], Wp[0][q][3], hw);
                fma2(accP[1][bb2], Wp[1][q][3], hw);
            }
        }

        // paired butterfly reduction over the 8 kr lanes (packed 64-bit adds)
        bool hi  = (kr & 4) != 0;
        bool md  = (kr & 2) != 0;
        bool lo  = (kr & 1) != 0;
        u64 gatep[2];
#pragma unroll
        for (int p = 0; p < 2; p++) {
            u64 t4[4];
#pragma unroll
            for (int b2 = 0; b2 < 4; b2++) {
                u64 keep = hi ? accP[p][b2 + 4] : accP[p][b2];
                u64 send = hi ? accP[p][b2]     : accP[p][b2 + 4];
                t4[b2] = add2(keep, __shfl_xor_sync(0xffffffffu, send, 4));
            }
            u64 t2[2];
#pragma unroll
            for (int b2 = 0; b2 < 2; b2++) {
                u64 keep = md ? t4[b2 + 2] : t4[b2];
                u64 send = md ? t4[b2]     : t4[b2 + 2];
                t2[b2] = add2(keep, __shfl_xor_sync(0xffffffffu, send, 2));
            }
            {
                u64 keep = lo ? t2[1] : t2[0];
                u64 send = lo ? t2[0] : t2[1];
                gatep[p] = add2(keep, __shfl_xor_sync(0xffffffffu, send, 1));
            }
        }

        float2 g01 = unpack2(gatep[0]);   // (i, f)
        float2 g23 = unpack2(gatep[1]);   // (g, o)
        float gi = g01.x + xw0;
        float gf = g01.y + xw1;
        float gc = g23.x + xw2;
        float go = g23.y + xw3;
        float i_ = fast_sigmoid(gi);
        float f_ = fast_sigmoid(gf);
        float g_ = fast_tanh(gc);
        float o_ = fast_sigmoid(go);
        c = fmaf(f_, c, i_ * g_);
        float h = o_ * fast_tanh(c);

        // multicast h into next buffer of all 8 cluster CTAs (padded index)
        unsigned laddr = smem_u32(&hsm[buf ^ 1][b][jg + s * 4]);
#pragma unroll
        for (int r = 0; r < 8; r++) st_cluster_f32(laddr, r, h);

        cluster_arrive();

        // overlapped with barrier: persist h, prefetch next xw
        Hout[((size_t)bglob * 512 + t) * 512 + dir * 256 + jg] = h;
        if (step + 1 < 512) {
            int tn_ = dir ? (511 - (step + 1)) : (step + 1);
            const float* xq = XW + ((size_t)tn_ * 64 + bglob) * 1024 + jg;
            xw0 = xq[0]; xw1 = xq[256]; xw2 = xq[512]; xw3 = xq[768];
        }

        cluster_wait();
        buf ^= 1;
    }
}

// ---------------------------------------------------------------------------
// Emissions: FEATS[m][n] = H1[m][:512] . fc_w[n][:] + fc_b[n]. Warp per row.
// ---------------------------------------------------------------------------
__global__ __launch_bounds__(256) void feats_kernel(
    const float* __restrict__ fcw, const float* __restrict__ fcb)
{
    __shared__ float wsm[KK * 512];
    int tid = threadIdx.x;
    for (int i = tid; i < KK * 512; i += 256) wsm[i] = fcw[i];
    __syncthreads();

    int warp = tid >> 5, lane = tid & 31;
    size_t row = (size_t)blockIdx.x * 8 + warp;
    const float* hr = d_H1 + row * 512;

    float hreg[16];
#pragma unroll
    for (int i = 0; i < 16; i++) hreg[i] = hr[lane + 32 * i];

#pragma unroll
    for (int n = 0; n < KK; n++) {
        float p = 0.f;
#pragma unroll
        for (int i = 0; i < 16; i++) p = fmaf(hreg[i], wsm[n * 512 + lane + 32 * i], p);
        p += __shfl_xor_sync(0xffffffffu, p, 16);
        p += __shfl_xor_sync(0xffffffffu, p, 8);
        p += __shfl_xor_sync(0xffffffffu, p, 4);
        p += __shfl_xor_sync(0xffffffffu, p, 2);
        p += __shfl_xor_sync(0xffffffffu, p, 1);
        if (lane == 0) d_FEATS[row * KK + n] = p + __ldg(&fcb[n]);
    }
}

// ---------------------------------------------------------------------------
// Viterbi, one warp per batch. fv in lanes (lane=tag). Strict '>' = first-max
// matching jnp.argmax. mode 0: out=[score(64)|path(64*512)]; 1: path; 2: score
// ---------------------------------------------------------------------------
__global__ __launch_bounds__(32) void viterbi_kernel(
    const float* __restrict__ trans, float* __restrict__ out, int mode)
{
    __shared__ unsigned char bp[512][16];
    int b = blockIdx.x, lane = threadIdx.x;
    int li = (lane < KK) ? lane : (KK - 1);

    float tr[KK];
#pragma unroll
    for (int p = 0; p < KK; p++) tr[p] = trans[li * KK + p];   // trans[next=li][prev=p]
    float trStop = trans[STOPP * KK + li];

    float fv = (lane < KK) ? ((lane == STARTT) ? 0.f : -1000.f) : -3.0e38f;
    const float* fb = d_FEATS + (size_t)b * 512 * KK;

    for (int t = 0; t < 512; t++) {
        float best = -3.0e38f; int bi = 0;
#pragma unroll
        for (int p = 0; p < KK; p++) {
            float fp = __shfl_sync(0xffffffffu, fv, p);
            float sc = fp + tr[p];
            if (sc > best) { best = sc; bi = p; }
        }
        if (lane < KK) bp[t][lane] = (unsigned char)bi;
        float ft = fb[t * KK + li];
        float nfv = best + ft;
        fv = (lane < KK) ? nfv : -3.0e38f;
    }
    __syncwarp();

    float term = (lane < KK) ? (fv + trStop) : -3.0e38f;
    float best = -3.0e38f; int bt = 0;
#pragma unroll
    for (int p = 0; p < KK; p++) {
        float v = __shfl_sync(0xffffffffu, term, p);
        if (v > best) { best = v; bt = p; }
    }
    __syncwarp();

    if (lane == 0) {
        float* scoreOut = nullptr; float* pathOut = nullptr;
        if (mode == 0)      { scoreOut = out; pathOut = out + 64; }
        else if (mode == 1) { pathOut = out; }
        else                { scoreOut = out; }
        if (scoreOut) scoreOut[b] = best;
        if (pathOut) {
            int tag = bt;
            pathOut[(size_t)b * 512 + 511] = (float)tag;
            for (int t = 511; t >= 1; t--) {
                tag = bp[t][tag];
                pathOut[(size_t)b * 512 + (t - 1)] = (float)tag;
            }
        }
    }
}

// ---------------------------------------------------------------------------
extern "C" void kernel_launch(void* const* d_in, const int* in_sizes, int n_in,
                              void* d_out, int out_size)
{
    const int*   sent  = (const int*)d_in[0];
    // d_in[1] = batch_lengths (all == T; unused)
    const float* emb   = (const float*)d_in[2];
    const float* fcw   = (const float*)d_in[3];
    const float* fcb   = (const float*)d_in[4];
    const float* trans = (const float*)d_in[5];
    const float* wih0f = (const float*)d_in[6];
    const float* whh0f = (const float*)d_in[7];
    const float* b0f   = (const float*)d_in[8];
    const float* wih0b = (const float*)d_in[9];
    const float* whh0b = (const float*)d_in[10];
    const float* b0b   = (const float*)d_in[11];
    const float* wih1f = (const float*)d_in[12];
    const float* whh1f = (const float*)d_in[13];
    const float* b1f   = (const float*)d_in[14];
    const float* wih1b = (const float*)d_in[15];
    const float* whh1b = (const float*)d_in[16];
    const float* b1b   = (const float*)d_in[17];
    float* out = (float*)d_out;

    int mode = 0;
    if (out_size == 64 * 512) mode = 1;         // path only
    else if (out_size == 64) mode = 2;          // score only
    // default: [score(64) | path(64*512)]

    dim3 pgrid(16, 256);
    proj_kernel<<<pgrid, 256>>>(sent, emb, wih0f, b0f, wih0b, b0b, 300, 0);
    rec_kernel<<<128, 256>>>(whh0f, whh0b, 0);
    proj_kernel<<<pgrid, 256>>>(sent, emb, wih1f, b1f, wih1b, b1b, 512, 1);
    rec_kernel<<<128, 256>>>(whh1f, whh1b, 1);
    feats_kernel<<<4096, 256>>>(fcw, fcb);
    viterbi_kernel<<<64, 32>>>(trans, out, mode);
}

// round 16
// speedup vs baseline: 1.0145x; 1.0145x over previous
#include <cuda_runtime.h>
#include <math.h>

#define TT 512
#define BB 64
#define HH 256
#define KK 11
#define STARTT 9
#define STOPP 10

typedef unsigned long long u64;
typedef unsigned int u32;

// ---------------- scratch (device globals: allocation-free rule) -----------
__device__ float d_XWF[(size_t)TT * BB * 1024];   // [T][B][4H] fwd input proj
__device__ float d_XWB[(size_t)TT * BB * 1024];   // [T][B][4H] bwd input proj
__device__ float d_H0[(size_t)BB * TT * 512];     // [B*T][2H] layer0 out (fwd|bwd)
__device__ float d_H1[(size_t)BB * TT * 512];     // [B*T][2H] layer1 out
__device__ float d_FEATS[(size_t)BB * TT * KK];   // [B*T][K] emissions

// ---------------- helpers --------------------------------------------------
__device__ __forceinline__ unsigned smem_u32(const void* p) {
    return (unsigned)__cvta_generic_to_shared(p);
}
__device__ __forceinline__ void st_cluster_f32(unsigned laddr, int rank, float v) {
    unsigned raddr;
    asm volatile("mapa.shared::cluster.u32 %0, %1, %2;" : "=r"(raddr) : "r"(laddr), "r"(rank));
    asm volatile("st.shared::cluster.f32 [%0], %1;" :: "r"(raddr), "f"(v) : "memory");
}
__device__ __forceinline__ void cluster_arrive() {
    asm volatile("barrier.cluster.arrive.aligned;" ::: "memory");
}
__device__ __forceinline__ void cluster_wait() {
    asm volatile("barrier.cluster.wait.aligned;" ::: "memory");
}
__device__ __forceinline__ float fast_sigmoid(float x) {
    return __fdividef(1.f, 1.f + __expf(-x));
}
__device__ __forceinline__ float fast_tanh(float x) {
    float xc = fminf(15.f, fmaxf(-15.f, x));
    float e = __expf(2.f * xc);
    return __fdividef(e - 1.f, e + 1.f);
}

// ---- packed fp32x2 (Blackwell FFMA2) — used by rec kernel ------------------
__device__ __forceinline__ u64 pack2(float lo, float hi) {
    u64 r; asm("mov.b64 %0, {%1, %2};" : "=l"(r) : "f"(lo), "f"(hi)); return r;
}
__device__ __forceinline__ float2 unpack2(u64 v) {
    float2 f; asm("mov.b64 {%0, %1}, %2;" : "=f"(f.x), "=f"(f.y) : "l"(v)); return f;
}
__device__ __forceinline__ void fma2(u64& d, u64 a, u64 b) {
    asm("fma.rn.f32x2 %0, %1, %2, %0;" : "+l"(d) : "l"(a), "l"(b));
}
__device__ __forceinline__ u64 add2(u64 a, u64 b) {
    u64 r; asm("add.rn.f32x2 %0, %1, %2;" : "=l"(r) : "l"(a), "l"(b)); return r;
}

// ---- tf32 helpers ----------------------------------------------------------
__device__ __forceinline__ u32 cvt_tf32(float x) {
    u32 r; asm("cvt.rna.tf32.f32 %0, %1;" : "=r"(r) : "f"(x)); return r;
}
__device__ __forceinline__ void split_tf32(float v, u32& hi, u32& lo) {
    hi = cvt_tf32(v);
    lo = cvt_tf32(v - __uint_as_float(hi));
}
__device__ __forceinline__ void mma_tf32(float* c, const u32* a, const u32* b) {
    asm volatile(
        "mma.sync.aligned.m16n8k8.row.col.f32.tf32.tf32.f32 "
        "{%0,%1,%2,%3}, {%4,%5,%6,%7}, {%8,%9}, {%0,%1,%2,%3};"
        : "+f"(c[0]), "+f"(c[1]), "+f"(c[2]), "+f"(c[3])
        : "r"(a[0]), "r"(a[1]), "r"(a[2]), "r"(a[3]), "r"(b[0]), "r"(b[1]));
}

// ---------------------------------------------------------------------------
// Input projection on TENSOR CORES (3xTF32): XW[t][b][n] = x[m].W[n] + bias[n]
//   layer 0: x[m] = emb[sent[m]], K=300 ; layer 1: x = d_H0 rows, K=512
// Tile 128x128xBK16, 256 thr = 8 warps, each warp owns 64(M)x32(N).
// Raw fp32 staged in smem (pad 132); tf32 hi/lo split at fragment load;
// 3 mma terms: hi*hi + lo*hi + hi*lo (err ~2^-22 rel).
// ---------------------------------------------------------------------------
#define APAD 132
__global__ __launch_bounds__(256) void proj_kernel(
    const int* __restrict__ sent, const float* __restrict__ emb,
    const float* __restrict__ Wf, const float* __restrict__ bf,
    const float* __restrict__ Wb, const float* __restrict__ bb_,
    int K, int layer)
{
    __shared__ float As[2][16][APAD];   // As[k][m] = X[m][k]
    __shared__ float Bs[2][16][APAD];   // Bs[k][n] = W[n][k]
    __shared__ int srow[128];

    int tid = threadIdx.x;
    int bx  = blockIdx.x;          // 0..15
    int by  = blockIdx.y;          // 0..255
    int m0  = by * 128;
    int dirb = bx >> 3;
    int ncol = (bx & 7) * 128;

    const float* W    = dirb ? Wb  : Wf;
    const float* bias = dirb ? bb_ : bf;
    float*       XW   = dirb ? d_XWB : d_XWF;

    if (layer == 0 && tid < 128) srow[tid] = sent[m0 + tid];
    __syncthreads();

    int mi = tid >> 1;            // 0..127
    int ks = (tid & 1) * 8;       // 0 or 8

    const float* arow;
    if (layer == 0) arow = emb + (size_t)srow[mi] * 300;
    else            arow = d_H0 + (size_t)(m0 + mi) * 512;
    const float* wrow = W + (size_t)(ncol + mi) * K;

    int wid  = tid >> 5, lane = tid & 31;
    int wm   = wid >> 2;            // 0..1 -> 64 M rows
    int wn   = wid & 3;             // 0..3 -> 32 N cols
    int m0w  = wm * 64;
    int n0w  = wn * 32;
    int gq   = lane >> 2;           // groupID 0..7
    int tq   = lane & 3;            // thread-in-group 0..3

    float c[4][4][4];               // [im][in][creg]
#pragma unroll
    for (int im = 0; im < 4; im++)
#pragma unroll
        for (int in = 0; in < 4; in++)
#pragma unroll
            for (int r = 0; r < 4; r++) c[im][in][r] = 0.f;

    const float4 z4 = make_float4(0.f, 0.f, 0.f, 0.f);
    int nk = (K + 15) >> 4;

    float4 pa0, pa1, pb0, pb1;
    {
        int k0 = ks;
        pa0 = (k0     < K) ? *(const float4*)(arow + k0)     : z4;
        pa1 = (k0 + 4 < K) ? *(const float4*)(arow + k0 + 4) : z4;
        pb0 = (k0     < K) ? *(const float4*)(wrow + k0)     : z4;
        pb1 = (k0 + 4 < K) ? *(const float4*)(wrow + k0 + 4) : z4;
    }
    As[0][ks + 0][mi] = pa0.x; As[0][ks + 1][mi] = pa0.y;
    As[0][ks + 2][mi] = pa0.z; As[0][ks + 3][mi] = pa0.w;
    As[0][ks + 4][mi] = pa1.x; As[0][ks + 5][mi] = pa1.y;
    As[0][ks + 6][mi] = pa1.z; As[0][ks + 7][mi] = pa1.w;
    Bs[0][ks + 0][mi] = pb0.x; Bs[0][ks + 1][mi] = pb0.y;
    Bs[0][ks + 2][mi] = pb0.z; Bs[0][ks + 3][mi] = pb0.w;
    Bs[0][ks + 4][mi] = pb1.x; Bs[0][ks + 5][mi] = pb1.y;
    Bs[0][ks + 6][mi] = pb1.z; Bs[0][ks + 7][mi] = pb1.w;
    __syncthreads();

    for (int it = 0; it < nk; ++it) {
        int cur = it & 1;

        if (it + 1 < nk) {
            int k0 = (it + 1) * 16 + ks;
            pa0 = (k0     < K) ? *(const float4*)(arow + k0)     : z4;
            pa1 = (k0 + 4 < K) ? *(const float4*)(arow + k0 + 4) : z4;
            pb0 = (k0     < K) ? *(const float4*)(wrow + k0)     : z4;
            pb1 = (k0 + 4 < K) ? *(const float4*)(wrow + k0 + 4) : z4;
        }

        const float* Ab = &As[cur][0][0];
        const float* Bb = &Bs[cur][0][0];

#pragma unroll
        for (int kk = 0; kk < 16; kk += 8) {
            // A fragments: a0 (row gq, col tq), a1 (row gq+8), a2 (col tq+4), a3 (both)
            u32 ahi[4][4], alo[4][4];
#pragma unroll
            for (int im = 0; im < 4; im++) {
                int mb = m0w + im * 16 + gq;
#pragma unroll
                for (int r = 0; r < 4; r++) {
                    int kidx = kk + tq + ((r >> 1) << 2);
                    int midx = mb + ((r & 1) << 3);
                    float v = Ab[kidx * APAD + midx];
                    split_tf32(v, ahi[im][r], alo[im][r]);
                }
            }
            // B fragments (col-major 8x8): b0 (row tq, col gq), b1 (row tq+4)
            u32 bhi[4][2], blo[4][2];
#pragma unroll
            for (int in = 0; in < 4; in++) {
                int nb = n0w + in * 8 + gq;
#pragma unroll
                for (int r = 0; r < 2; r++) {
                    int kidx = kk + tq + (r << 2);
                    float v = Bb[kidx * APAD + nb];
                    split_tf32(v, bhi[in][r], blo[in][r]);
                }
            }
            // 3xTF32: hi*hi + lo*hi + hi*lo
#pragma unroll
            for (int im = 0; im < 4; im++)
#pragma unroll
                for (int in = 0; in < 4; in++) {
                    mma_tf32(c[im][in], ahi[im], bhi[in]);
                    mma_tf32(c[im][in], alo[im], bhi[in]);
                    mma_tf32(c[im][in], ahi[im], blo[in]);
                }
        }

        if (it + 1 < nk) {
            int nb2 = cur ^ 1;
            As[nb2][ks + 0][mi] = pa0.x; As[nb2][ks + 1][mi] = pa0.y;
            As[nb2][ks + 2][mi] = pa0.z; As[nb2][ks + 3][mi] = pa0.w;
            As[nb2][ks + 4][mi] = pa1.x; As[nb2][ks + 5][mi] = pa1.y;
            As[nb2][ks + 6][mi] = pa1.z; As[nb2][ks + 7][mi] = pa1.w;
            Bs[nb2][ks + 0][mi] = pb0.x; Bs[nb2][ks + 1][mi] = pb0.y;
            Bs[nb2][ks + 2][mi] = pb0.z; Bs[nb2][ks + 3][mi] = pb0.w;
            Bs[nb2][ks + 4][mi] = pb1.x; Bs[nb2][ks + 5][mi] = pb1.y;
            Bs[nb2][ks + 6][mi] = pb1.z; Bs[nb2][ks + 7][mi] = pb1.w;
            __syncthreads();
        }
    }

    // epilogue: c[im][in] -> rows m0w+im*16+gq (+8), cols n0w+in*8+2*tq (+1)
#pragma unroll
    for (int im = 0; im < 4; im++) {
#pragma unroll
        for (int in = 0; in < 4; in++) {
            int col = ncol + n0w + in * 8 + (tq << 1);
            float2 bz = *(const float2*)&bias[col];
            int row0 = m0w + im * 16 + gq;
            // row0
            {
                int mm = m0 + row0;
                int b_ = mm >> 9, t_ = mm & 511;
                float* orow = XW + ((size_t)t_ * 64 + b_) * 1024;
                float2 o = make_float2(c[im][in][0] + bz.x, c[im][in][1] + bz.y);
                *(float2*)(orow + col) = o;
            }
            // row0 + 8
            {
                int mm = m0 + row0 + 8;
                int b_ = mm >> 9, t_ = mm & 511;
                float* orow = XW + ((size_t)t_ * 64 + b_) * 1024;
                float2 o = make_float2(c[im][in][2] + bz.x, c[im][in][3] + bz.y);
                *(float2*)(orow + col) = o;
            }
        }
    }
}

// ---------------------------------------------------------------------------
// Recurrent LSTM (unchanged from best). grid=128 CTAs, cluster 8, 256 thr.
// ---------------------------------------------------------------------------
__global__ __launch_bounds__(256) __cluster_dims__(8, 1, 1)
void rec_kernel(const float* __restrict__ whhF, const float* __restrict__ whhB, int outSel)
{
    __shared__ float hsm[2][8][288];   // [buf][batch][k padded: k + (k>>5)*4]

    int cta = blockIdx.x;
    int s   = cta & 7;
    int cl  = cta >> 3;
    int dir = cl >> 3;      // 0 fwd, 1 bwd
    int bg  = cl & 7;

    const float* XW   = dir ? d_XWB : d_XWF;
    const float* Whh  = dir ? whhB  : whhF;
    float*       Hout = outSel ? d_H1 : d_H0;

    int tid  = threadIdx.x;
    int w    = tid >> 5, lane = tid & 31;
    int jsub = lane >> 3, kr = lane & 7;
    int jl   = w * 4 + jsub;
    int jg   = s * 32 + jl;
    int b    = kr;
    int bglob = bg * 8 + b;

    // load 4 gate rows' k-slices, pack along gate pairs
    u64 Wp[2][8][4];
    {
        const float* w0 = Whh + (size_t)(0 * 256 + jg) * 256 + kr * 32;
        const float* w1 = Whh + (size_t)(1 * 256 + jg) * 256 + kr * 32;
        const float* w2 = Whh + (size_t)(2 * 256 + jg) * 256 + kr * 32;
        const float* w3 = Whh + (size_t)(3 * 256 + jg) * 256 + kr * 32;
#pragma unroll
        for (int q = 0; q < 8; q++) {
            float4 a = *(const float4*)(w0 + q * 4);
            float4 bq = *(const float4*)(w1 + q * 4);
            float4 cq = *(const float4*)(w2 + q * 4);
            float4 dq = *(const float4*)(w3 + q * 4);
            Wp[0][q][0] = pack2(a.x, bq.x); Wp[0][q][1] = pack2(a.y, bq.y);
            Wp[0][q][2] = pack2(a.z, bq.z); Wp[0][q][3] = pack2(a.w, bq.w);
            Wp[1][q][0] = pack2(cq.x, dq.x); Wp[1][q][1] = pack2(cq.y, dq.y);
            Wp[1][q][2] = pack2(cq.z, dq.z); Wp[1][q][3] = pack2(cq.w, dq.w);
        }
    }

    for (int i = tid; i < 2 * 8 * 288; i += 256) (&hsm[0][0][0])[i] = 0.f;
    float c = 0.f;
    __syncthreads();
    cluster_arrive();

    // prefetch xw for step 0 (overlaps barrier wait)
    int t0 = dir ? 511 : 0;
    const float* xwp = XW + ((size_t)t0 * 64 + bglob) * 1024 + jg;
    float xw0 = xwp[0], xw1 = xwp[256], xw2 = xwp[512], xw3 = xwp[768];

    cluster_wait();                    // zeros + peers ready

    int buf = 0;
    for (int step = 0; step < 512; ++step) {
        int t = dir ? (511 - step) : step;

        u64 accP[2][8];
#pragma unroll
        for (int p = 0; p < 2; p++)
#pragma unroll
            for (int q = 0; q < 8; q++) accP[p][q] = 0ull;

        const float* hb = &hsm[buf][0][0];
#pragma unroll
        for (int q = 0; q < 8; q++) {
#pragma unroll
            for (int bb2 = 0; bb2 < 8; bb2++) {
                float4 hv = *(const float4*)(hb + bb2 * 288 + kr * 36 + q * 4);
                u64 hx = pack2(hv.x, hv.x);
                u64 hy = pack2(hv.y, hv.y);
                u64 hz = pack2(hv.z, hv.z);
                u64 hw = pack2(hv.w, hv.w);
                fma2(accP[0][bb2], Wp[0][q][0], hx);
                fma2(accP[1][bb2], Wp[1][q][0], hx);
                fma2(accP[0][bb2], Wp[0][q][1], hy);
                fma2(accP[1][bb2], Wp[1][q][1], hy);
                fma2(accP[0][bb2], Wp[0][q][2], hz);
                fma2(accP[1][bb2], Wp[1][q][2], hz);
                fma2(accP[0][bb2], Wp[0][q][3], hw);
                fma2(accP[1][bb2], Wp[1][q][3], hw);
            }
        }

        // paired butterfly reduction over the 8 kr lanes (packed 64-bit adds)
        bool hi  = (kr & 4) != 0;
        bool md  = (kr & 2) != 0;
        bool lo  = (kr & 1) != 0;
        u64 gatep[2];
#pragma unroll
        for (int p = 0; p < 2; p++) {
            u64 t4[4];
#pragma unroll
            for (int b2 = 0; b2 < 4; b2++) {
                u64 keep = hi ? accP[p][b2 + 4] : accP[p][b2];
                u64 send = hi ? accP[p][b2]     : accP[p][b2 + 4];
                t4[b2] = add2(keep, __shfl_xor_sync(0xffffffffu, send, 4));
            }
            u64 t2[2];
#pragma unroll
            for (int b2 = 0; b2 < 2; b2++) {
                u64 keep = md ? t4[b2 + 2] : t4[b2];
                u64 send = md ? t4[b2]     : t4[b2 + 2];
                t2[b2] = add2(keep, __shfl_xor_sync(0xffffffffu, send, 2));
            }
            {
                u64 keep = lo ? t2[1] : t2[0];
                u64 send = lo ? t2[0] : t2[1];
                gatep[p] = add2(keep, __shfl_xor_sync(0xffffffffu, send, 1));
            }
        }

        float2 g01 = unpack2(gatep[0]);   // (i, f)
        float2 g23 = unpack2(gatep[1]);   // (g, o)
        float gi = g01.x + xw0;
        float gf = g01.y + xw1;
        float gc = g23.x + xw2;
        float go = g23.y + xw3;
        float i_ = fast_sigmoid(gi);
        float f_ = fast_sigmoid(gf);
        float g_ = fast_tanh(gc);
        float o_ = fast_sigmoid(go);
        c = fmaf(f_, c, i_ * g_);
        float h = o_ * fast_tanh(c);

        // multicast h into next buffer of all 8 cluster CTAs (padded index)
        unsigned laddr = smem_u32(&hsm[buf ^ 1][b][jg + s * 4]);
#pragma unroll
        for (int r = 0; r < 8; r++) st_cluster_f32(laddr, r, h);

        cluster_arrive();

        // overlapped with barrier: persist h, prefetch next xw
        Hout[((size_t)bglob * 512 + t) * 512 + dir * 256 + jg] = h;
        if (step + 1 < 512) {
            int tn_ = dir ? (511 - (step + 1)) : (step + 1);
            const float* xq = XW + ((size_t)tn_ * 64 + bglob) * 1024 + jg;
            xw0 = xq[0]; xw1 = xq[256]; xw2 = xq[512]; xw3 = xq[768];
        }

        cluster_wait();
        buf ^= 1;
    }
}

// ---------------------------------------------------------------------------
// Emissions: FEATS[m][n] = H1[m][:512] . fc_w[n][:] + fc_b[n]. Warp per row.
// ---------------------------------------------------------------------------
__global__ __launch_bounds__(256) void feats_kernel(
    const float* __restrict__ fcw, const float* __restrict__ fcb)
{
    __shared__ float wsm[KK * 512];
    int tid = threadIdx.x;
    for (int i = tid; i < KK * 512; i += 256) wsm[i] = fcw[i];
    __syncthreads();

    int warp = tid >> 5, lane = tid & 31;
    size_t row = (size_t)blockIdx.x * 8 + warp;
    const float* hr = d_H1 + row * 512;

    float hreg[16];
#pragma unroll
    for (int i = 0; i < 16; i++) hreg[i] = hr[lane + 32 * i];

#pragma unroll
    for (int n = 0; n < KK; n++) {
        float p = 0.f;
#pragma unroll
        for (int i = 0; i < 16; i++) p = fmaf(hreg[i], wsm[n * 512 + lane + 32 * i], p);
        p += __shfl_xor_sync(0xffffffffu, p, 16);
        p += __shfl_xor_sync(0xffffffffu, p, 8);
        p += __shfl_xor_sync(0xffffffffu, p, 4);
        p += __shfl_xor_sync(0xffffffffu, p, 2);
        p += __shfl_xor_sync(0xffffffffu, p, 1);
        if (lane == 0) d_FEATS[row * KK + n] = p + __ldg(&fcb[n]);
    }
}

// ---------------------------------------------------------------------------
// Viterbi, one warp per batch. fv in lanes (lane=tag). Strict '>' = first-max
// matching jnp.argmax. mode 0: out=[score(64)|path(64*512)]; 1: path; 2: score
// ---------------------------------------------------------------------------
__global__ __launch_bounds__(32) void viterbi_kernel(
    const float* __restrict__ trans, float* __restrict__ out, int mode)
{
    __shared__ unsigned char bp[512][16];
    int b = blockIdx.x, lane = threadIdx.x;
    int li = (lane < KK) ? lane : (KK - 1);

    float tr[KK];
#pragma unroll
    for (int p = 0; p < KK; p++) tr[p] = trans[li * KK + p];   // trans[next=li][prev=p]
    float trStop = trans[STOPP * KK + li];

    float fv = (lane < KK) ? ((lane == STARTT) ? 0.f : -1000.f) : -3.0e38f;
    const float* fb = d_FEATS + (size_t)b * 512 * KK;

    for (int t = 0; t < 512; t++) {
        float best = -3.0e38f; int bi = 0;
#pragma unroll
        for (int p = 0; p < KK; p++) {
            float fp = __shfl_sync(0xffffffffu, fv, p);
            float sc = fp + tr[p];
            if (sc > best) { best = sc; bi = p; }
        }
        if (lane < KK) bp[t][lane] = (unsigned char)bi;
        float ft = fb[t * KK + li];
        float nfv = best + ft;
        fv = (lane < KK) ? nfv : -3.0e38f;
    }
    __syncwarp();

    float term = (lane < KK) ? (fv + trStop) : -3.0e38f;
    float best = -3.0e38f; int bt = 0;
#pragma unroll
    for (int p = 0; p < KK; p++) {
        float v = __shfl_sync(0xffffffffu, term, p);
        if (v > best) { best = v; bt = p; }
    }
    __syncwarp();

    if (lane == 0) {
        float* scoreOut = nullptr; float* pathOut = nullptr;
        if (mode == 0)      { scoreOut = out; pathOut = out + 64; }
        else if (mode == 1) { pathOut = out; }
        else                { scoreOut = out; }
        if (scoreOut) scoreOut[b] = best;
        if (pathOut) {
            int tag = bt;
            pathOut[(size_t)b * 512 + 511] = (float)tag;
            for (int t = 511; t >= 1; t--) {
                tag = bp[t][tag];
                pathOut[(size_t)b * 512 + (t - 1)] = (float)tag;
            }
        }
    }
}

// ---------------------------------------------------------------------------
extern "C" void kernel_launch(void* const* d_in, const int* in_sizes, int n_in,
                              void* d_out, int out_size)
{
    const int*   sent  = (const int*)d_in[0];
    // d_in[1] = batch_lengths (all == T; unused)
    const float* emb   = (const float*)d_in[2];
    const float* fcw   = (const float*)d_in[3];
    const float* fcb   = (const float*)d_in[4];
    const float* trans = (const float*)d_in[5];
    const float* wih0f = (const float*)d_in[6];
    const float* whh0f = (const float*)d_in[7];
    const float* b0f   = (const float*)d_in[8];
    const float* wih0b = (const float*)d_in[9];
    const float* whh0b = (const float*)d_in[10];
    const float* b0b   = (const float*)d_in[11];
    const float* wih1f = (const float*)d_in[12];
    const float* whh1f = (const float*)d_in[13];
    const float* b1f   = (const float*)d_in[14];
    const float* wih1b = (const float*)d_in[15];
    const float* whh1b = (const float*)d_in[16];
    const float* b1b   = (const float*)d_in[17];
    float* out = (float*)d_out;

    int mode = 0;
    if (out_size == 64 * 512) mode = 1;         // path only
    else if (out_size == 64) mode = 2;          // score only
    // default: [score(64) | path(64*512)]

    dim3 pgrid(16, 256);
    proj_kernel<<<pgrid, 256>>>(sent, emb, wih0f, b0f, wih0b, b0b, 300, 0);
    rec_kernel<<<128, 256>>>(whh0f, whh0b, 0);
    proj_kernel<<<pgrid, 256>>>(sent, emb, wih1f, b1f, wih1b, b1b, 512, 1);
    rec_kernel<<<128, 256>>>(whh1f, whh1b, 1);
    feats_kernel<<<4096, 256>>>(fcw, fcb);
    viterbi_kernel<<<64, 32>>>(trans, out, mode);
}